// round 12
// baseline (speedup 1.0000x reference)
#include <cuda_runtime.h>
#include <cstdint>

#define TT 16384
#define CC 1024
#define NROWS 128           // tail rows in stats table (window provably < 25)
#define N_ITERS 30
#define GRID 144            // <= 148 SMs -> one wave, safe software grid barrier
#define NTH 256

__device__ float g_up[128 * CC];      // per-A-block partial u (512 KB)
__device__ float g_u[CC];             // full u (deep fallback only)
__device__ float g_patt[NROWS * 16];  // [l][chunk] partial att dots
__device__ float g_av[NROWS];
__device__ int   g_barc[2 * 32];      // one cache line per phase; left 0 after launch

#define SCALE 3.125e-5f     // 0.001 / sqrt(1024)

__device__ __forceinline__ float neg_inf() { return __int_as_float(0xff800000); }

__device__ __forceinline__ void gbar_arrive(int ph) {
    __syncthreads();
    if (threadIdx.x == 0) {
        __threadfence();
        atomicAdd(&g_barc[ph << 5], 1);
    }
}
__device__ __forceinline__ void gbar_wait(int ph, int count) {
    if (threadIdx.x == 0) {
        while (*(volatile int*)&g_barc[ph << 5] < count) { }
        __threadfence();
    }
    __syncthreads();
}

__device__ __forceinline__ float wred_sum(float v) {
#pragma unroll
    for (int o = 16; o; o >>= 1) v += __shfl_xor_sync(0xffffffffu, v, o);
    return v;
}

__global__ void __launch_bounds__(NTH, 1)
k_all(const float* __restrict__ x, const float* __restrict__ W,
      const float* __restrict__ alpha, const float* __restrict__ beta,
      float* __restrict__ out)
{
    __shared__ float  sq[8];                   // this block's 8 q values (stage A)
    __shared__ float  sredf[256];              // C: pgroup reduction
    __shared__ float  su[64];                  // C: this block's u chunk
    __shared__ float  sS[NROWS + 1], sB[NROWS + 1], sY[NROWS + 1];
    __shared__ float  bu_tab[NROWS + 1];
    __shared__ float  tia[32];
    __shared__ float  red[8];
    __shared__ float  fm[8], fs[8], fb[8], fy[8];
    __shared__ float  smax, salpha, sbeta;

    const int b = blockIdx.x, t = threadIdx.x;
    const int lane = t & 31, wid = t >> 5;

    if (b == 0 && t == 0) { salpha = *alpha; sbeta = *beta; }

    // ========= STAGE A (blocks 0-127): q for 8 rows -> partial u ==============
    if (b < 128) {
        const int i0 = b << 3;
        const float* Wk = W + (size_t)CC * CC;

        // coalesced front-batch of this block's 8 full W_k rows
        float4 wk[8];
#pragma unroll
        for (int k = 0; k < 8; k++)
            wk[k] = ((const float4*)(Wk + (size_t)(i0 + k) * CC))[t];

        // q[i0+wid] = x_last . W_q[i0+wid]
        const float4* xl4 = (const float4*)(x + (size_t)(TT - 1) * CC);
        const float4* wr4 = (const float4*)(W + (size_t)(i0 + wid) * CC);
        float4 xa[8], wa[8];
#pragma unroll
        for (int c = 0; c < 8; c++) xa[c] = xl4[c * 32 + lane];
#pragma unroll
        for (int c = 0; c < 8; c++) wa[c] = wr4[c * 32 + lane];
        float s = 0.f;
#pragma unroll
        for (int c = 0; c < 8; c++)
            s += xa[c].x * wa[c].x + xa[c].y * wa[c].y + xa[c].z * wa[c].z + xa[c].w * wa[c].w;
        s = wred_sum(s);
        if (lane == 0) sq[wid] = s;
        __syncthreads();                       // also publishes salpha/sbeta (block 0)

        // partial u over this block's 8 i-rows, all 1024 j (thread t owns j4 = t)
        float4 acc = make_float4(0.f, 0.f, 0.f, 0.f);
#pragma unroll
        for (int k = 0; k < 8; k++) {
            float q = sq[k];
            acc.x += q * wk[k].x; acc.y += q * wk[k].y;
            acc.z += q * wk[k].z; acc.w += q * wk[k].w;
        }
        ((float4*)g_up)[b * 256 + t] = acc;
    } else {
        // av for 8 tail rows (blocks 128-143); also warms L2 with the tail x rows
        int l = ((b - 128) << 3) + wid;
        const float4* xr4 = (const float4*)(x + (size_t)(TT - 1 - l) * CC);
        const float4* wv4 = (const float4*)(W + (size_t)(2 * CC) * CC);
        float4 xa[8], wa[8];
#pragma unroll
        for (int c = 0; c < 8; c++) xa[c] = xr4[c * 32 + lane];
#pragma unroll
        for (int c = 0; c < 8; c++) wa[c] = wv4[c * 32 + lane];
        float s = 0.f;
#pragma unroll
        for (int c = 0; c < 8; c++)
            s += xa[c].x * wa[c].x + xa[c].y * wa[c].y + xa[c].z * wa[c].z + xa[c].w * wa[c].w;
        s = wred_sum(s);
        if (lane == 0) g_av[l] = s;
    }

    // block 0: 2/a table while still parallel
    if (b == 0 && t < N_ITERS) tia[t] = 2.0f / (salpha + (float)t);

    gbar_arrive(0);
    if (b >= 16) return;                        // 128 blocks exit; bar1 counts 16 only
    gbar_wait(0, GRID);

    // ========= STAGE C (blocks 0-15): u chunk + partial att for all 128 l =====
    const int j0 = b << 6;                      // 64 columns per block
    {
        // reduce this chunk of u over the 128 partials (L2; coalesced per warp)
        int jj = t & 63, pg = t >> 6;           // 4 p-groups x 32 partials
        float s = 0.f;
#pragma unroll 8
        for (int p = 0; p < 32; p++)
            s += g_up[(size_t)(pg * 32 + p) * CC + j0 + jj];
        sredf[pg * 64 + jj] = s;
        __syncthreads();
        if (t < 64) {
            float u = sredf[t] + sredf[64 + t] + sredf[128 + t] + sredf[192 + t];
            su[t] = u;
            g_u[j0 + t] = u;                    // for the (never-taken) deep fallback
        }
        __syncthreads();

        // partial att: thread (l = t>>1, h = t&1) dots 32 columns (x rows L2-hot)
        int l = t >> 1, h = t & 1;
        const float4* xr = (const float4*)(x + (size_t)(TT - 1 - l) * CC + j0 + 32 * h);
        const float4* uu = (const float4*)(su + 32 * h);
        float d = 0.f;
#pragma unroll
        for (int c = 0; c < 8; c++) {
            float4 xa = xr[c];
            float4 ua = uu[c];
            d += xa.x * ua.x + xa.y * ua.y + xa.z * ua.z + xa.w * ua.w;
        }
        d += __shfl_xor_sync(0xffffffffu, d, 1);
        if (h == 0) g_patt[l * 16 + b] = d;
    }
    gbar_arrive(1);
    if (b != 0) return;

    // av prefetch while waiting for the 16 C arrivals
    float v0 = (t < NROWS) ? g_av[t] : 0.f;
    gbar_wait(1, 16);
    if (t == 0) { g_barc[0] = 0; g_barc[32] = 0; }     // replay-safe

    // ========= STAGE D (block 0): att assembly + stats + serial recurrence ====
    float a0 = neg_inf();
    if (t > 0 && t < NROWS) {
        const float4* pr = (const float4*)(g_patt + t * 16);
        float4 p0 = pr[0], p1 = pr[1], p2 = pr[2], p3 = pr[3];
        float sum = (p0.x + p0.y + p0.z + p0.w) + (p1.x + p1.y + p1.z + p1.w)
                  + (p2.x + p2.y + p2.z + p2.w) + (p3.x + p3.y + p3.z + p3.w);
        a0 = sum * SCALE;
    }

    float lm = a0;
#pragma unroll
    for (int o = 16; o; o >>= 1) lm = fmaxf(lm, __shfl_xor_sync(0xffffffffu, lm, o));
    if (lane == 0) red[wid] = lm;
    __syncthreads();
    if (t == 0) {
        float m0 = red[0];
#pragma unroll
        for (int i = 1; i < 8; i++) m0 = fmaxf(m0, red[i]);
        smax = m0;
    }
    __syncthreads();
    const float m = smax;

    if (t < NROWS) {
        float e0 = __expf(a0 - m);
        float ps = e0, pb = e0 * (float)t, py = e0 * v0;
#pragma unroll
        for (int o = 1; o < 32; o <<= 1) {
            float ts = __shfl_up_sync(0xffffffffu, ps, o);
            float tb = __shfl_up_sync(0xffffffffu, pb, o);
            float ty = __shfl_up_sync(0xffffffffu, py, o);
            if (lane >= o) { ps += ts; pb += tb; py += ty; }
        }
        if (lane == 31) { fs[wid] = ps; fb[wid] = pb; fy[wid] = py; }
        __syncthreads();
        if (t == 0) {
            float cs = 0.f, cb = 0.f, cy = 0.f;
#pragma unroll
            for (int i = 0; i < 4; i++) {
                float ns = fs[i], nb = fb[i], ny = fy[i];
                fs[i] = cs; fb[i] = cb; fy[i] = cy;
                cs += ns; cb += nb; cy += ny;
            }
        }
        __syncthreads();
        ps += fs[wid]; pb += fb[wid]; py += fy[wid];
        sS[t + 1] = ps; sB[t + 1] = pb; sY[t + 1] = py;
        bu_tab[t + 1] = pb / ps;
        if (t == 0) { sS[0] = 0.f; sB[0] = 0.f; sY[0] = 0.f; bu_tab[0] = 0.f; }
    } else {
        __syncthreads(); __syncthreads();
    }
    __syncthreads();

    // serial recurrence: kk = 2 + bb*(2/a);  bb += bu_tab[w]
    float bb = sbeta, k_old = 0.f;
    float s_f = 1.f, ys_f = 0.f;
    for (int it = 0; it < N_ITERS; it++) {
        float kk = fmaf(bb, tia[it], 2.0f);
        int w = __float2int_ru(kk);
        if (w < 1) w = 1;

        float s, bs, ys;
        if (w <= NROWS) {
            s = sS[w]; bs = sB[w]; ys = sY[w];
            bb += bu_tab[w];
        } else {
            if (w > TT) w = TT;
            // exact deep fallback (never taken for these inputs): online softmax
            const float4* u4  = (const float4*)g_u;
            const float4* wv4 = (const float4*)(W + (size_t)(2 * CC) * CC);
            float m_r = neg_inf(), s_r = 0.f, b_r = 0.f, y_r = 0.f;
            for (int l = wid; l < w; l += 8) {
                if (l == 0) continue;                    // masked position
                const float4* xr = (const float4*)(x + (size_t)(TT - 1 - l) * CC);
                float du = 0.f, dv = 0.f;
                for (int c = 0; c < 8; c++) {
                    float4 xa = xr[c * 32 + lane];
                    float4 ub = u4[c * 32 + lane];
                    float4 vb = wv4[c * 32 + lane];
                    du += xa.x * ub.x + xa.y * ub.y + xa.z * ub.z + xa.w * ub.w;
                    dv += xa.x * vb.x + xa.y * vb.y + xa.z * vb.z + xa.w * vb.w;
                }
                du = wred_sum(du); dv = wred_sum(dv);
                float att = du * SCALE;
                float mn = fmaxf(m_r, att);
                float ro = __expf(m_r - mn);
                float e  = __expf(att - mn);
                s_r = s_r * ro + e;
                b_r = b_r * ro + e * (float)l;
                y_r = y_r * ro + e * dv;
                m_r = mn;
            }
            if (lane == 0) { fm[wid] = m_r; fs[wid] = s_r; fb[wid] = b_r; fy[wid] = y_r; }
            __syncthreads();
            float M = fm[0];
            for (int i = 1; i < 8; i++) M = fmaxf(M, fm[i]);
            s = 0.f; bs = 0.f; ys = 0.f;
            for (int i = 0; i < 8; i++) {
                float r2 = __expf(fm[i] - M);
                s  += fs[i] * r2;
                bs += fb[i] * r2;
                ys += fy[i] * r2;
            }
            __syncthreads();
            bb += bs / s;
        }

        s_f = s; ys_f = ys;
        bool stop = (kk > (float)TT) || (kk < k_old);
        k_old = kk;
        if (stop) break;
    }
    if (t == 0) out[0] = ys_f / s_f;
}

// ---------------------------------------------------------------------------
extern "C" void kernel_launch(void* const* d_in, const int* in_sizes, int n_in,
                              void* d_out, int out_size) {
    const float* x = nullptr;
    const float* W = nullptr;
    const float* alpha = nullptr;
    const float* beta = nullptr;
    for (int i = 0; i < n_in; i++) {
        if (in_sizes[i] == TT * CC)                x = (const float*)d_in[i];
        else if (in_sizes[i] == (2 * CC + 1) * CC) W = (const float*)d_in[i];
        else if (in_sizes[i] == 1) {
            if (!alpha) alpha = (const float*)d_in[i];
            else        beta  = (const float*)d_in[i];
        }
    }
    float* out = (float*)d_out;
    k_all<<<GRID, NTH>>>(x, W, alpha, beta, out);
}